// round 9
// baseline (speedup 1.0000x reference)
#include <cuda_runtime.h>
#include <math.h>
#include <stdint.h>

// ---------------- problem constants ----------------
#define HIDDEN   768
#define MLPH     3072
#define HEADS    12
#define HEAD_DIM 64
#define BATCH    16
#define SEQ      1024
#define MTOK     (BATCH * SEQ)

// ---------------- scratch (device globals; no allocation) ----------------
__device__ float g_xn  [(size_t)MTOK * HIDDEN];
__device__ float g_qkv [(size_t)3 * MTOK * HIDDEN];   // [q | k | v], each [MTOK][768]
__device__ float g_attn[(size_t)MTOK * HIDDEN];
__device__ float g_x1  [(size_t)MTOK * HIDDEN];
__device__ float g_h   [(size_t)MTOK * MLPH];
__device__ float g_w1t [(size_t)MLPH * HIDDEN];
__device__ float g_w2t [(size_t)HIDDEN * MLPH];
__device__ float g_wqkv[(size_t)3 * HIDDEN * HIDDEN];
__device__ float g_wo  [(size_t)HIDDEN * HIDDEN];

// ---------------- helpers ----------------
__device__ __forceinline__ uint32_t f2tf(float f) {
    uint32_t r; asm("cvt.rna.tf32.f32 %0, %1;" : "=r"(r) : "f"(f)); return r;
}
__device__ __forceinline__ float tfr(float f) { return __uint_as_float(f2tf(f)); }
__device__ __forceinline__ uint32_t smem_u32(const void* p) {
    uint32_t a;
    asm("{ .reg .u64 t; cvta.to.shared.u64 t, %1; cvt.u32.u64 %0, t; }" : "=r"(a) : "l"(p));
    return a;
}
__device__ __forceinline__ void ldsm4(uint32_t* r, uint32_t addr) {
    asm volatile("ldmatrix.sync.aligned.m8n8.x4.shared.b16 {%0,%1,%2,%3}, [%4];"
                 : "=r"(r[0]), "=r"(r[1]), "=r"(r[2]), "=r"(r[3]) : "r"(addr));
}
__device__ __forceinline__ void cp16(uint32_t saddr, const void* g) {
    asm volatile("cp.async.ca.shared.global [%0], [%1], 16;" :: "r"(saddr), "l"(g) : "memory");
}
__device__ __forceinline__ void cp_commit() {
    asm volatile("cp.async.commit_group;" ::: "memory");
}
__device__ __forceinline__ void cp_wait0() {
    asm volatile("cp.async.wait_group 0;" ::: "memory");
}
__device__ __forceinline__ void mma_tf32(float* d, const uint32_t* a, const uint32_t* b) {
    asm volatile("mma.sync.aligned.m16n8k8.row.col.f32.tf32.tf32.f32 "
                 "{%0,%1,%2,%3}, {%4,%5,%6,%7}, {%8,%9}, {%0,%1,%2,%3};"
                 : "+f"(d[0]), "+f"(d[1]), "+f"(d[2]), "+f"(d[3])
                 : "r"(a[0]), "r"(a[1]), "r"(a[2]), "r"(a[3]), "r"(b[0]), "r"(b[1]));
}
__device__ __forceinline__ float warp_sum(float v) {
    #pragma unroll
    for (int o = 16; o; o >>= 1) v += __shfl_xor_sync(0xffffffffu, v, o);
    return v;
}

// ---------------- prep: pack QKV weights (tf32-rounded) ----------------
__global__ __launch_bounds__(256)
void qkvpack_k(const float* __restrict__ wq, const float* __restrict__ wk,
               const float* __restrict__ wv, float* __restrict__ dst)
{
    const int N4 = HIDDEN * HIDDEN / 4;
    int i = blockIdx.x * 256 + threadIdx.x;
    if (i >= 3 * N4) return;
    const float* src = (i < N4) ? wq : (i < 2 * N4) ? wk : wv;
    int j = (i < N4) ? i : (i < 2 * N4) ? i - N4 : i - 2 * N4;
    float4 v = reinterpret_cast<const float4*>(src)[j];
    v.x = tfr(v.x); v.y = tfr(v.y); v.z = tfr(v.z); v.w = tfr(v.w);
    reinterpret_cast<float4*>(dst)[i] = v;
}

__global__ __launch_bounds__(256)
void roundcpy_k(const float* __restrict__ in, float* __restrict__ out, int n4)
{
    int i = blockIdx.x * 256 + threadIdx.x;
    if (i < n4) {
        float4 v = reinterpret_cast<const float4*>(in)[i];
        v.x = tfr(v.x); v.y = tfr(v.y); v.z = tfr(v.z); v.w = tfr(v.w);
        reinterpret_cast<float4*>(out)[i] = v;
    }
}

// ---------------- LayerNorm (tf32-rounded output) ----------------
__global__ __launch_bounds__(256)
void ln_k(const float* __restrict__ x, const float* __restrict__ g,
          const float* __restrict__ b, float* __restrict__ out)
{
    long row = blockIdx.x;
    const float* xr = x + row * (long)HIDDEN;
    int tid = threadIdx.x;
    float v0 = xr[tid], v1 = xr[tid + 256], v2 = xr[tid + 512];
    float s  = v0 + v1 + v2;
    float s2 = v0 * v0 + v1 * v1 + v2 * v2;
    __shared__ float sh[18];
    s = warp_sum(s); s2 = warp_sum(s2);
    int w = tid >> 5, l = tid & 31;
    if (!l) { sh[w] = s; sh[w + 8] = s2; }
    __syncthreads();
    if (tid == 0) {
        float ts = 0.f, ts2 = 0.f;
        #pragma unroll
        for (int i = 0; i < 8; i++) { ts += sh[i]; ts2 += sh[i + 8]; }
        float mu  = ts * (1.0f / HIDDEN);
        float var = ts2 * (1.0f / HIDDEN) - mu * mu;
        sh[16] = mu; sh[17] = rsqrtf(var + 1e-5f);
    }
    __syncthreads();
    float mu = sh[16], inv = sh[17];
    float* o = out + row * (long)HIDDEN;
    o[tid]       = tfr((v0 - mu) * inv * g[tid]       + b[tid]);
    o[tid + 256] = tfr((v1 - mu) * inv * g[tid + 256] + b[tid + 256]);
    o[tid + 512] = tfr((v2 - mu) * inv * g[tid + 512] + b[tid + 512]);
}

// ---------------- transpose + tf32 round (weights) ----------------
__global__ __launch_bounds__(256)
void transpose_k(const float* __restrict__ in, int ldi,
                 float* __restrict__ out, int ldo)
{
    __shared__ float t[32][33];
    int c0 = blockIdx.x * 32, r0 = blockIdx.y * 32;
    int tx = threadIdx.x & 31, ty = threadIdx.x >> 5;
    #pragma unroll
    for (int i = ty; i < 32; i += 8)
        t[i][tx] = in[(long)(r0 + i) * ldi + c0 + tx];
    __syncthreads();
    #pragma unroll
    for (int i = ty; i < 32; i += 8)
        out[(long)(c0 + i) * ldo + r0 + tx] = tfr(t[tx][i]);
}

// ---------------- flash attention (pipelined, dense q/k/v) ----------------
#define FPV 133
#define KWORDS 8192       // one K/Q buffer: 128 rows x 64 words, swizzled
#define VWORDS (64 * FPV) // 8512

__global__ __launch_bounds__(256)
void flash_k(const float* __restrict__ Qb, const float* __restrict__ Kb,
             const float* __restrict__ Vb_g, float* __restrict__ Og)
{
    extern __shared__ uint32_t sm[];
    uint32_t* Qs = sm;                       // [128][64] swizzled
    uint32_t* Ks = sm + KWORDS;              // 2 x [128][64] swizzled
    uint32_t* Vs = sm + 3 * KWORDS;          // 2 x [64][FPV]

    int tid = threadIdx.x, lane = tid & 31, wid = tid >> 5;
    int qr = lane >> 2, qc = lane & 3;
    int z = blockIdx.y;
    int b = z / HEADS, h = z - b * HEADS;
    int q0 = blockIdx.x * 128;
    long tokbase = (long)b * SEQ + q0;

    const float* Qp = Qb + tokbase * HIDDEN + h * HEAD_DIM;
    const float* Kp = Kb + (long)b * SEQ * HIDDEN + h * HEAD_DIM;
    const float* Vp = Vb_g + (long)b * SEQ * HIDDEN + h * HEAD_DIM;

    uint32_t qsb = smem_u32(Qs), ksb = smem_u32(Ks);

    // prologue: cp.async Q + K0, scalar V0
    #pragma unroll
    for (int i = 0; i < 8; i++) {
        int idx = tid + i * 256; int r = idx >> 4, u = idx & 15;
        int up = u ^ (r & 7);
        cp16(qsb + ((r * 64 + up * 4) << 2), Qp + (long)r * HIDDEN + u * 4);
        cp16(ksb + ((r * 64 + up * 4) << 2), Kp + (long)r * HIDDEN + u * 4);
    }
    cp_commit();
    #pragma unroll
    for (int i = 0; i < 8; i++) {
        int idx = tid + i * 256; int t = idx >> 4, c = idx & 15;
        float4 v = *reinterpret_cast<const float4*>(Vp + (long)t * HIDDEN + c * 4);
        uint32_t* d = Vs + (4 * c) * FPV + t;
        d[0]       = __float_as_uint(v.x);
        d[FPV]     = __float_as_uint(v.y);
        d[2 * FPV] = __float_as_uint(v.z);
        d[3 * FPV] = __float_as_uint(v.w);
    }
    cp_wait0();
    __syncthreads();

    int rQ = wid * 16 + ((lane >> 3) & 1) * 8 + (lane & 7);
    int q7 = rQ & 7, hiQ = lane >> 4;
    int rK = ((lane >> 4) * 8) + (lane & 7);
    int k7 = rK & 7, hiK = (lane >> 3) & 1;

    uint32_t qf[8][4];
    #pragma unroll
    for (int ks = 0; ks < 8; ks++)
        ldsm4(qf[ks], qsb + ((rQ * 64 + ((ks * 2 + hiQ) ^ q7) * 4) << 2));

    float oa[8][4];
    #pragma unroll
    for (int i = 0; i < 8; i++)
        #pragma unroll
        for (int e = 0; e < 4; e++) oa[i][e] = 0.f;
    float mA = -1e30f, mB = -1e30f, lA = 0.f, lB = 0.f;
    const float scale = 0.125f;

    for (int ch = 0; ch < SEQ / 128; ch++) {
        int buf = ch & 1;
        uint32_t kbuf = ksb + ((buf * KWORDS) << 2);
        const uint32_t* Vb = Vs + buf * VWORDS;

        // S = Q @ K^T
        float sa[16][4];
        #pragma unroll
        for (int i = 0; i < 16; i++)
            #pragma unroll
            for (int e = 0; e < 4; e++) sa[i][e] = 0.f;
        #pragma unroll
        for (int ks = 0; ks < 8; ks++) {
            int uK = (((ks * 2 + hiK) ^ k7) * 4);
            #pragma unroll
            for (int ntp = 0; ntp < 8; ntp++) {
                uint32_t kf[4];
                ldsm4(kf, kbuf + (((rK + ntp * 16) * 64 + uK) << 2));
                mma_tf32(sa[2 * ntp + 0], qf[ks], kf);
                mma_tf32(sa[2 * ntp + 1], qf[ks], kf + 2);
            }
        }

        // prefetch next K (async; overlaps softmax + PV)
        if (ch + 1 < SEQ / 128) {
            const float* Kn = Kp + (long)(ch + 1) * 128 * HIDDEN;
            uint32_t dst = ksb + (((buf ^ 1) * KWORDS) << 2);
            #pragma unroll
            for (int i = 0; i < 8; i++) {
                int idx = tid + i * 256; int r = idx >> 4, u = idx & 15;
                int up = u ^ (r & 7);
                cp16(dst + ((r * 64 + up * 4) << 2), Kn + (long)r * HIDDEN + u * 4);
            }
            cp_commit();
        }

        // online softmax
        float rmA = -1e30f, rmB = -1e30f;
        #pragma unroll
        for (int nt = 0; nt < 16; nt++) {
            rmA = fmaxf(rmA, fmaxf(sa[nt][0], sa[nt][1]));
            rmB = fmaxf(rmB, fmaxf(sa[nt][2], sa[nt][3]));
        }
        rmA = fmaxf(rmA, __shfl_xor_sync(0xffffffffu, rmA, 1));
        rmA = fmaxf(rmA, __shfl_xor_sync(0xffffffffu, rmA, 2));
        rmB = fmaxf(rmB, __shfl_xor_sync(0xffffffffu, rmB, 1));
        rmB = fmaxf(rmB, __shfl_xor_sync(0xffffffffu, rmB, 2));
        float mAn = fmaxf(mA, rmA), mBn = fmaxf(mB, rmB);
        float aA = __expf((mA - mAn) * scale), aB = __expf((mB - mBn) * scale);
        float sA = 0.f, sB = 0.f;
        #pragma unroll
        for (int nt = 0; nt < 16; nt++) {
            sa[nt][0] = __expf((sa[nt][0] - mAn) * scale);
            sa[nt][1] = __expf((sa[nt][1] - mAn) * scale);
            sa[nt][2] = __expf((sa[nt][2] - mBn) * scale);
            sa[nt][3] = __expf((sa[nt][3] - mBn) * scale);
            sA += sa[nt][0] + sa[nt][1];
            sB += sa[nt][2] + sa[nt][3];
        }
        sA += __shfl_xor_sync(0xffffffffu, sA, 1);
        sA += __shfl_xor_sync(0xffffffffu, sA, 2);
        sB += __shfl_xor_sync(0xffffffffu, sB, 1);
        sB += __shfl_xor_sync(0xffffffffu, sB, 2);
        lA = aA * lA + sA;  lB = aB * lB + sB;
        mA = mAn;  mB = mBn;
        #pragma unroll
        for (int nt = 0; nt < 8; nt++) {
            oa[nt][0] *= aA; oa[nt][1] *= aA;
            oa[nt][2] *= aB; oa[nt][3] *= aB;
        }

        // stage next V into other buffer (LDG latency covered by PV below)
        if (ch + 1 < SEQ / 128) {
            const float* Vn = Vp + (long)(ch + 1) * 128 * HIDDEN;
            uint32_t* Vd = Vs + (buf ^ 1) * VWORDS;
            #pragma unroll
            for (int i = 0; i < 8; i++) {
                int idx = tid + i * 256; int t = idx >> 4, c = idx & 15;
                float4 v = *reinterpret_cast<const float4*>(Vn + (long)t * HIDDEN + c * 4);
                uint32_t* d = Vd + (4 * c) * FPV + t;
                d[0]       = __float_as_uint(v.x);
                d[FPV]     = __float_as_uint(v.y);
                d[2 * FPV] = __float_as_uint(v.z);
                d[3 * FPV] = __float_as_uint(v.w);
            }
        }

        // O += P @ V
        int s0 = (lane & ~3) | (qc >> 1);
        int s1 = s0 + 2;
        bool hi = qc & 1;
        #pragma unroll
        for (int kk = 0; kk < 16; kk++) {
            uint32_t p0 = f2tf(sa[kk][0]), p1 = f2tf(sa[kk][1]);
            uint32_t p2 = f2tf(sa[kk][2]), p3 = f2tf(sa[kk][3]);
            uint32_t u0 = __shfl_sync(0xffffffffu, p0, s0);
            uint32_t u1 = __shfl_sync(0xffffffffu, p1, s0);
            uint32_t v0 = __shfl_sync(0xffffffffu, p2, s0);
            uint32_t v1 = __shfl_sync(0xffffffffu, p3, s0);
            uint32_t w0 = __shfl_sync(0xffffffffu, p0, s1);
            uint32_t w1 = __shfl_sync(0xffffffffu, p1, s1);
            uint32_t x0 = __shfl_sync(0xffffffffu, p2, s1);
            uint32_t x1 = __shfl_sync(0xffffffffu, p3, s1);
            uint32_t af[4];
            af[0] = hi ? u1 : u0;  af[1] = hi ? v1 : v0;
            af[2] = hi ? w1 : w0;  af[3] = hi ? x1 : x0;
            #pragma unroll
            for (int nt = 0; nt < 8; nt++) {
                const uint32_t* p = Vb + (nt * 8 + qr) * FPV + kk * 8 + qc;
                uint32_t bf[2] = { p[0], p[4] };
                mma_tf32(oa[nt], af, bf);
            }
        }

        cp_wait0();
        __syncthreads();
    }

    // epilogue (rounded: feeds WO GEMM)
    float rA = 1.f / lA, rB = 1.f / lB;
    long rowA = tokbase + wid * 16 + qr;
    float* OA = Og + rowA * HIDDEN + h * HEAD_DIM;
    float* OB = OA + 8 * HIDDEN;
    #pragma unroll
    for (int nt = 0; nt < 8; nt++) {
        int col = nt * 8 + 2 * qc;
        *reinterpret_cast<float2*>(OA + col) = make_float2(tfr(oa[nt][0] * rA), tfr(oa[nt][1] * rA));
        *reinterpret_cast<float2*>(OB + col) = make_float2(tfr(oa[nt][2] * rB), tfr(oa[nt][3] * rB));
    }
}

// ---------------- cp.async TF32 GEMM, 128x128, 2 CTAs/SM ----------------
// EPI: 0 store rounded; 1 +bias+resid; 2 +bias,GELU rounded;
//      3 store rounded into segmented output (seg = n0/HIDDEN, dense ld HIDDEN)
template<int EPI>
__global__ __launch_bounds__(256, 2)
void gemm_ca(const float* __restrict__ A, int lda,
             const float* __restrict__ B, int ldb,
             float* __restrict__ C, int ldc, int K,
             const float* __restrict__ bias,
             const float* __restrict__ resid, int ldr)
{
    constexpr int MT = 4, NT = 4;
    constexpr int BUF = 8192;
    extern __shared__ uint32_t sm[];
    uint32_t sbase = smem_u32(sm);

    int tid = threadIdx.x, lane = tid & 31, wid = tid >> 5;
    int wr = wid >> 2, wc = wid & 3;
    int m0 = blockIdx.y * 128, n0 = blockIdx.x * 128;

    const float* Ag = A + (long)m0 * lda;
    const float* Bg = B + (long)n0 * ldb;

    if (EPI == 3) {                       // segmented dense output (q|k|v)
        int seg = n0 / HIDDEN;
        C += (long)seg * MTOK * HIDDEN;
        n0 -= seg * HIDDEN;
    }

    int srow = tid >> 3, sc = tid & 7;
    int rA = wr * 64 + ((lane >> 3) & 1) * 8 + (lane & 7);
    int rB = wc * 32 + (lane >> 4) * 8 + (lane & 7);
    int a7 = rA & 7, b7 = rB & 7;
    int hiA = lane >> 4, hiB = (lane >> 3) & 1;

    float acc[MT][NT][4];
    #pragma unroll
    for (int i = 0; i < MT; i++)
        #pragma unroll
        for (int j = 0; j < NT; j++)
            #pragma unroll
            for (int e = 0; e < 4; e++) acc[i][j][e] = 0.f;

    int nCh = K >> 5;

    #pragma unroll
    for (int i = 0; i < 4; i++) {
        int row = srow + i * 32;
        int u = sc ^ (row & 7);
        cp16(sbase + ((row * 32 + u * 4) << 2), Ag + (long)row * lda + sc * 4);
        cp16(sbase + ((4096 + row * 32 + u * 4) << 2), Bg + (long)row * ldb + sc * 4);
    }
    cp_commit();

    for (int c = 0; c < nCh; ++c) {
        int buf = c & 1;
        cp_wait0();
        __syncthreads();
        if (c + 1 < nCh) {
            const float* An = Ag + (c + 1) * 32;
            const float* Bn = Bg + (c + 1) * 32;
            uint32_t dst = sbase + (((buf ^ 1) * BUF) << 2);
            #pragma unroll
            for (int i = 0; i < 4; i++) {
                int row = srow + i * 32;
                int u = sc ^ (row & 7);
                cp16(dst + ((row * 32 + u * 4) << 2), An + (long)row * lda + sc * 4);
                cp16(dst + ((4096 + row * 32 + u * 4) << 2), Bn + (long)row * ldb + sc * 4);
            }
            cp_commit();
        }

        uint32_t aB = sbase + ((buf * BUF) << 2);
        uint32_t bB = aB + (4096 << 2);

        #pragma unroll
        for (int ks = 0; ks < 4; ++ks) {
            uint32_t af[MT][4], bf[NT][2];
            int uA = ((ks * 2 + hiA) ^ a7) * 4;
            int uB = ((ks * 2 + hiB) ^ b7) * 4;
            #pragma unroll
            for (int mt = 0; mt < MT; mt++)
                ldsm4(af[mt], aB + (((rA + mt * 16) * 32 + uA) << 2));
            #pragma unroll
            for (int ntp = 0; ntp < 2; ntp++)
                ldsm4(&bf[2 * ntp][0], bB + (((rB + ntp * 16) * 32 + uB) << 2));
            #pragma unroll
            for (int mt = 0; mt < MT; mt++)
                #pragma unroll
                for (int nt = 0; nt < NT; nt++)
                    mma_tf32(acc[mt][nt], af[mt], bf[nt]);
        }
        __syncthreads();
    }

    int qr = lane >> 2, qc = lane & 3;
    #pragma unroll
    for (int mt = 0; mt < MT; mt++) {
        #pragma unroll
        for (int half = 0; half < 2; half++) {
            int row = m0 + wr * 64 + mt * 16 + qr + half * 8;
            float* Crow = C + (long)row * ldc;
            const float* Rrow = (EPI == 1) ? (resid + (long)row * ldr) : nullptr;
            #pragma unroll
            for (int nt = 0; nt < NT; nt++) {
                int col = n0 + wc * 32 + nt * 8 + 2 * qc;
                float v0 = acc[mt][nt][half * 2 + 0];
                float v1 = acc[mt][nt][half * 2 + 1];
                if (EPI == 1) {
                    v0 += bias[col]     + Rrow[col];
                    v1 += bias[col + 1] + Rrow[col + 1];
                } else if (EPI == 2) {
                    v0 += bias[col];
                    v1 += bias[col + 1];
                    v0 = tfr(0.5f * v0 * (1.0f + erff(v0 * 0.70710678118654752f)));
                    v1 = tfr(0.5f * v1 * (1.0f + erff(v1 * 0.70710678118654752f)));
                } else {
                    v0 = tfr(v0); v1 = tfr(v1);
                }
                *reinterpret_cast<float2*>(&Crow[col]) = make_float2(v0, v1);
            }
        }
    }
}

// ---------------- launcher ----------------
extern "C" void kernel_launch(void* const* d_in, const int* in_sizes, int n_in,
                              void* d_out, int out_size)
{
    const float* x    = (const float*)d_in[0];
    const float* ln1g = (const float*)d_in[1];
    const float* ln1b = (const float*)d_in[2];
    const float* wq   = (const float*)d_in[3];
    const float* wk   = (const float*)d_in[4];
    const float* wv   = (const float*)d_in[5];
    const float* wo   = (const float*)d_in[6];
    const float* bo   = (const float*)d_in[7];
    const float* ln2g = (const float*)d_in[8];
    const float* ln2b = (const float*)d_in[9];
    const float* w1   = (const float*)d_in[10];
    const float* b1   = (const float*)d_in[11];
    const float* w2   = (const float*)d_in[12];
    const float* b2   = (const float*)d_in[13];
    float* out = (float*)d_out;

    float *xn, *qkv, *attn, *x1, *hm, *w1t, *w2t, *rwqkv, *rwo;
    cudaGetSymbolAddress((void**)&xn,    g_xn);
    cudaGetSymbolAddress((void**)&qkv,   g_qkv);
    cudaGetSymbolAddress((void**)&attn,  g_attn);
    cudaGetSymbolAddress((void**)&x1,    g_x1);
    cudaGetSymbolAddress((void**)&hm,    g_h);
    cudaGetSymbolAddress((void**)&w1t,   g_w1t);
    cudaGetSymbolAddress((void**)&w2t,   g_w2t);
    cudaGetSymbolAddress((void**)&rwqkv, g_wqkv);
    cudaGetSymbolAddress((void**)&rwo,   g_wo);

    float* qb = qkv;
    float* kb = qkv + (size_t)MTOK * HIDDEN;
    float* vb = qkv + (size_t)2 * MTOK * HIDDEN;

    const int SMGE = 2 * 8192 * 4;                              // 65536
    const int SMFL = (3 * KWORDS + 2 * VWORDS) * 4;             // 166400
    cudaFuncSetAttribute((const void*)gemm_ca<0>, cudaFuncAttributeMaxDynamicSharedMemorySize, SMGE);
    cudaFuncSetAttribute((const void*)gemm_ca<1>, cudaFuncAttributeMaxDynamicSharedMemorySize, SMGE);
    cudaFuncSetAttribute((const void*)gemm_ca<2>, cudaFuncAttributeMaxDynamicSharedMemorySize, SMGE);
    cudaFuncSetAttribute((const void*)gemm_ca<3>, cudaFuncAttributeMaxDynamicSharedMemorySize, SMGE);
    cudaFuncSetAttribute((const void*)flash_k, cudaFuncAttributeMaxDynamicSharedMemorySize, SMFL);

    // prep
    int nw = HIDDEN * HIDDEN / 4;
    qkvpack_k<<<(3 * nw + 255) / 256, 256>>>(wq, wk, wv, rwqkv);
    roundcpy_k<<<(nw + 255) / 256, 256>>>(wo, rwo, nw);
    transpose_k<<<dim3(MLPH / 32, HIDDEN / 32), 256>>>(w1, MLPH, w1t, HIDDEN);
    transpose_k<<<dim3(HIDDEN / 32, MLPH / 32), 256>>>(w2, HIDDEN, w2t, MLPH);

    // 1. LN1
    ln_k<<<MTOK, 256>>>(x, ln1g, ln1b, xn);

    // 2. fused QKV (M=16384, N=2304, K=768) -> dense q|k|v segments
    gemm_ca<3><<<dim3(3 * HIDDEN / 128, MTOK / 128), 256, SMGE>>>(
        xn, HIDDEN, rwqkv, HIDDEN, qb, HIDDEN, HIDDEN, nullptr, nullptr, 0);

    // 3. fused attention
    flash_k<<<dim3(SEQ / 128, BATCH * HEADS), 256, SMFL>>>(qb, kb, vb, attn);

    // 4. x1 = attn @ wo^T + bo + x
    dim3 gH(HIDDEN / 128, MTOK / 128);
    gemm_ca<1><<<gH, 256, SMGE>>>(attn, HIDDEN, rwo, HIDDEN, x1, HIDDEN, HIDDEN, bo, x, HIDDEN);

    // 5. LN2
    ln_k<<<MTOK, 256>>>(x1, ln2g, ln2b, xn);

    // 6. h = gelu(xn @ w1 + b1)
    gemm_ca<2><<<dim3(MLPH / 128, MTOK / 128), 256, SMGE>>>(
        xn, HIDDEN, w1t, HIDDEN, hm, MLPH, HIDDEN, b1, nullptr, 0);

    // 7. out = h @ w2 + b2 + x1
    gemm_ca<1><<<gH, 256, SMGE>>>(hm, MLPH, w2t, MLPH, out, HIDDEN, MLPH, b2, x1, HIDDEN);
}

// round 10
// speedup vs baseline: 1.0325x; 1.0325x over previous
#include <cuda_runtime.h>
#include <math.h>
#include <stdint.h>

// ---------------- problem constants ----------------
#define HIDDEN   768
#define MLPH     3072
#define HEADS    12
#define HEAD_DIM 64
#define BATCH    16
#define SEQ      1024
#define MTOK     (BATCH * SEQ)

// ---------------- scratch (device globals; no allocation) ----------------
__device__ float g_xn  [(size_t)MTOK * HIDDEN];
__device__ float g_qkv [(size_t)3 * MTOK * HIDDEN];   // [q | k | v]
__device__ float g_attn[(size_t)MTOK * HIDDEN];
__device__ float g_x1  [(size_t)MTOK * HIDDEN];
__device__ float g_h   [(size_t)MTOK * MLPH];
__device__ float g_w1t [(size_t)MLPH * HIDDEN];
__device__ float g_w2t [(size_t)HIDDEN * MLPH];
__device__ float g_wqkv[(size_t)3 * HIDDEN * HIDDEN];
__device__ float g_wo  [(size_t)HIDDEN * HIDDEN];

// ---------------- helpers ----------------
__device__ __forceinline__ uint32_t f2tf(float f) {
    uint32_t r; asm("cvt.rna.tf32.f32 %0, %1;" : "=r"(r) : "f"(f)); return r;
}
__device__ __forceinline__ float tfr(float f) { return __uint_as_float(f2tf(f)); }
__device__ __forceinline__ uint32_t smem_u32(const void* p) {
    uint32_t a;
    asm("{ .reg .u64 t; cvta.to.shared.u64 t, %1; cvt.u32.u64 %0, t; }" : "=r"(a) : "l"(p));
    return a;
}
__device__ __forceinline__ void ldsm4(uint32_t* r, uint32_t addr) {
    asm volatile("ldmatrix.sync.aligned.m8n8.x4.shared.b16 {%0,%1,%2,%3}, [%4];"
                 : "=r"(r[0]), "=r"(r[1]), "=r"(r[2]), "=r"(r[3]) : "r"(addr));
}
__device__ __forceinline__ void cp16(uint32_t saddr, const void* g) {
    asm volatile("cp.async.ca.shared.global [%0], [%1], 16;" :: "r"(saddr), "l"(g) : "memory");
}
__device__ __forceinline__ void cp_commit() {
    asm volatile("cp.async.commit_group;" ::: "memory");
}
__device__ __forceinline__ void cp_wait0() {
    asm volatile("cp.async.wait_group 0;" ::: "memory");
}
__device__ __forceinline__ void mma_tf32(float* d, const uint32_t* a, const uint32_t* b) {
    asm volatile("mma.sync.aligned.m16n8k8.row.col.f32.tf32.tf32.f32 "
                 "{%0,%1,%2,%3}, {%4,%5,%6,%7}, {%8,%9}, {%0,%1,%2,%3};"
                 : "+f"(d[0]), "+f"(d[1]), "+f"(d[2]), "+f"(d[3])
                 : "r"(a[0]), "r"(a[1]), "r"(a[2]), "r"(a[3]), "r"(b[0]), "r"(b[1]));
}
__device__ __forceinline__ float warp_sum(float v) {
    #pragma unroll
    for (int o = 16; o; o >>= 1) v += __shfl_xor_sync(0xffffffffu, v, o);
    return v;
}

// ---------------- prep: pack QKV weights (tf32-rounded) ----------------
__global__ __launch_bounds__(256)
void qkvpack_k(const float* __restrict__ wq, const float* __restrict__ wk,
               const float* __restrict__ wv, float* __restrict__ dst)
{
    const int N4 = HIDDEN * HIDDEN / 4;
    int i = blockIdx.x * 256 + threadIdx.x;
    if (i >= 3 * N4) return;
    const float* src = (i < N4) ? wq : (i < 2 * N4) ? wk : wv;
    int j = (i < N4) ? i : (i < 2 * N4) ? i - N4 : i - 2 * N4;
    float4 v = reinterpret_cast<const float4*>(src)[j];
    v.x = tfr(v.x); v.y = tfr(v.y); v.z = tfr(v.z); v.w = tfr(v.w);
    reinterpret_cast<float4*>(dst)[i] = v;
}

__global__ __launch_bounds__(256)
void roundcpy_k(const float* __restrict__ in, float* __restrict__ out, int n4)
{
    int i = blockIdx.x * 256 + threadIdx.x;
    if (i < n4) {
        float4 v = reinterpret_cast<const float4*>(in)[i];
        v.x = tfr(v.x); v.y = tfr(v.y); v.z = tfr(v.z); v.w = tfr(v.w);
        reinterpret_cast<float4*>(out)[i] = v;
    }
}

// ---------------- LayerNorm (tf32-rounded output) ----------------
__global__ __launch_bounds__(256)
void ln_k(const float* __restrict__ x, const float* __restrict__ g,
          const float* __restrict__ b, float* __restrict__ out)
{
    long row = blockIdx.x;
    const float* xr = x + row * (long)HIDDEN;
    int tid = threadIdx.x;
    float v0 = xr[tid], v1 = xr[tid + 256], v2 = xr[tid + 512];
    float s  = v0 + v1 + v2;
    float s2 = v0 * v0 + v1 * v1 + v2 * v2;
    __shared__ float sh[18];
    s = warp_sum(s); s2 = warp_sum(s2);
    int w = tid >> 5, l = tid & 31;
    if (!l) { sh[w] = s; sh[w + 8] = s2; }
    __syncthreads();
    if (tid == 0) {
        float ts = 0.f, ts2 = 0.f;
        #pragma unroll
        for (int i = 0; i < 8; i++) { ts += sh[i]; ts2 += sh[i + 8]; }
        float mu  = ts * (1.0f / HIDDEN);
        float var = ts2 * (1.0f / HIDDEN) - mu * mu;
        sh[16] = mu; sh[17] = rsqrtf(var + 1e-5f);
    }
    __syncthreads();
    float mu = sh[16], inv = sh[17];
    float* o = out + row * (long)HIDDEN;
    o[tid]       = tfr((v0 - mu) * inv * g[tid]       + b[tid]);
    o[tid + 256] = tfr((v1 - mu) * inv * g[tid + 256] + b[tid + 256]);
    o[tid + 512] = tfr((v2 - mu) * inv * g[tid + 512] + b[tid + 512]);
}

// ---------------- transpose + tf32 round (weights) ----------------
__global__ __launch_bounds__(256)
void transpose_k(const float* __restrict__ in, int ldi,
                 float* __restrict__ out, int ldo)
{
    __shared__ float t[32][33];
    int c0 = blockIdx.x * 32, r0 = blockIdx.y * 32;
    int tx = threadIdx.x & 31, ty = threadIdx.x >> 5;
    #pragma unroll
    for (int i = ty; i < 32; i += 8)
        t[i][tx] = in[(long)(r0 + i) * ldi + c0 + tx];
    __syncthreads();
    #pragma unroll
    for (int i = ty; i < 32; i += 8)
        out[(long)(c0 + i) * ldo + r0 + tx] = tfr(t[tx][i]);
}

// ---------------- flash attention (fully async K+V staging) ----------------
// V stored [key][dim] padded to VROW words: PV B-frag = 2 scalar LDS, bank map
// (4*qc + qr) % 32 is a bijection -> conflict-free. K/Q swizzled for ldmatrix.
#define VROW  68
#define KWORDS 8192              // 128 rows x 64 words
#define VWORDS (128 * VROW)      // 8704

__global__ __launch_bounds__(256)
void flash_k(const float* __restrict__ Qb, const float* __restrict__ Kb,
             const float* __restrict__ Vg, float* __restrict__ Og)
{
    extern __shared__ uint32_t sm[];
    uint32_t* Qs = sm;                     // [128][64] swizzled
    uint32_t* Ks = sm + KWORDS;            // 2 x [128][64] swizzled
    uint32_t* Vs = sm + 3 * KWORDS;        // 2 x [128][VROW]

    int tid = threadIdx.x, lane = tid & 31, wid = tid >> 5;
    int qr = lane >> 2, qc = lane & 3;
    int z = blockIdx.y;
    int b = z / HEADS, h = z - b * HEADS;
    int q0 = blockIdx.x * 128;
    long tokbase = (long)b * SEQ + q0;

    const float* Qp = Qb + tokbase * HIDDEN + h * HEAD_DIM;
    const float* Kp = Kb + (long)b * SEQ * HIDDEN + h * HEAD_DIM;
    const float* Vp = Vg + (long)b * SEQ * HIDDEN + h * HEAD_DIM;

    uint32_t qsb = smem_u32(Qs), ksb = smem_u32(Ks), vsb = smem_u32(Vs);

    // prologue: async Q + K0 + V0
    #pragma unroll
    for (int i = 0; i < 8; i++) {
        int idx = tid + i * 256; int r = idx >> 4, u = idx & 15;
        int up = u ^ (r & 7);
        cp16(qsb + ((r * 64 + up * 4) << 2), Qp + (long)r * HIDDEN + u * 4);
        cp16(ksb + ((r * 64 + up * 4) << 2), Kp + (long)r * HIDDEN + u * 4);
        cp16(vsb + ((r * VROW + u * 4) << 2), Vp + (long)r * HIDDEN + u * 4);
    }
    cp_commit();
    cp_wait0();
    __syncthreads();

    int rQ = wid * 16 + ((lane >> 3) & 1) * 8 + (lane & 7);
    int q7 = rQ & 7, hiQ = lane >> 4;
    int rK = ((lane >> 4) * 8) + (lane & 7);
    int k7 = rK & 7, hiK = (lane >> 3) & 1;

    uint32_t qf[8][4];
    #pragma unroll
    for (int ks = 0; ks < 8; ks++)
        ldsm4(qf[ks], qsb + ((rQ * 64 + ((ks * 2 + hiQ) ^ q7) * 4) << 2));

    float oa[8][4];
    #pragma unroll
    for (int i = 0; i < 8; i++)
        #pragma unroll
        for (int e = 0; e < 4; e++) oa[i][e] = 0.f;
    float mA = -1e30f, mB = -1e30f, lA = 0.f, lB = 0.f;
    const float scale = 0.125f;

    for (int ch = 0; ch < SEQ / 128; ch++) {
        int buf = ch & 1;
        uint32_t kbuf = ksb + ((buf * KWORDS) << 2);
        const uint32_t* Vb = Vs + buf * VWORDS;

        // S = Q @ K^T
        float sa[16][4];
        #pragma unroll
        for (int i = 0; i < 16; i++)
            #pragma unroll
            for (int e = 0; e < 4; e++) sa[i][e] = 0.f;
        #pragma unroll
        for (int ks = 0; ks < 8; ks++) {
            int uK = (((ks * 2 + hiK) ^ k7) * 4);
            #pragma unroll
            for (int ntp = 0; ntp < 8; ntp++) {
                uint32_t kf[4];
                ldsm4(kf, kbuf + (((rK + ntp * 16) * 64 + uK) << 2));
                mma_tf32(sa[2 * ntp + 0], qf[ks], kf);
                mma_tf32(sa[2 * ntp + 1], qf[ks], kf + 2);
            }
        }

        // async prefetch K(c+1) + V(c+1); lands during softmax + PV
        if (ch + 1 < SEQ / 128) {
            const float* Kn = Kp + (long)(ch + 1) * 128 * HIDDEN;
            const float* Vn = Vp + (long)(ch + 1) * 128 * HIDDEN;
            uint32_t kdst = ksb + (((buf ^ 1) * KWORDS) << 2);
            uint32_t vdst = vsb + (((buf ^ 1) * VWORDS) << 2);
            #pragma unroll
            for (int i = 0; i < 8; i++) {
                int idx = tid + i * 256; int r = idx >> 4, u = idx & 15;
                int up = u ^ (r & 7);
                cp16(kdst + ((r * 64 + up * 4) << 2), Kn + (long)r * HIDDEN + u * 4);
                cp16(vdst + ((r * VROW + u * 4) << 2), Vn + (long)r * HIDDEN + u * 4);
            }
            cp_commit();
        }

        // online softmax
        float rmA = -1e30f, rmB = -1e30f;
        #pragma unroll
        for (int nt = 0; nt < 16; nt++) {
            rmA = fmaxf(rmA, fmaxf(sa[nt][0], sa[nt][1]));
            rmB = fmaxf(rmB, fmaxf(sa[nt][2], sa[nt][3]));
        }
        rmA = fmaxf(rmA, __shfl_xor_sync(0xffffffffu, rmA, 1));
        rmA = fmaxf(rmA, __shfl_xor_sync(0xffffffffu, rmA, 2));
        rmB = fmaxf(rmB, __shfl_xor_sync(0xffffffffu, rmB, 1));
        rmB = fmaxf(rmB, __shfl_xor_sync(0xffffffffu, rmB, 2));
        float mAn = fmaxf(mA, rmA), mBn = fmaxf(mB, rmB);
        float aA = __expf((mA - mAn) * scale), aB = __expf((mB - mBn) * scale);
        float sA = 0.f, sB = 0.f;
        #pragma unroll
        for (int nt = 0; nt < 16; nt++) {
            sa[nt][0] = __expf((sa[nt][0] - mAn) * scale);
            sa[nt][1] = __expf((sa[nt][1] - mAn) * scale);
            sa[nt][2] = __expf((sa[nt][2] - mBn) * scale);
            sa[nt][3] = __expf((sa[nt][3] - mBn) * scale);
            sA += sa[nt][0] + sa[nt][1];
            sB += sa[nt][2] + sa[nt][3];
        }
        sA += __shfl_xor_sync(0xffffffffu, sA, 1);
        sA += __shfl_xor_sync(0xffffffffu, sA, 2);
        sB += __shfl_xor_sync(0xffffffffu, sB, 1);
        sB += __shfl_xor_sync(0xffffffffu, sB, 2);
        lA = aA * lA + sA;  lB = aB * lB + sB;
        mA = mAn;  mB = mBn;
        #pragma unroll
        for (int nt = 0; nt < 8; nt++) {
            oa[nt][0] *= aA; oa[nt][1] *= aA;
            oa[nt][2] *= aB; oa[nt][3] *= aB;
        }

        // O += P @ V  (B frags: V[key][dim] rows, conflict-free scalar LDS)
        int s0 = (lane & ~3) | (qc >> 1);
        int s1 = s0 + 2;
        bool hi = qc & 1;
        #pragma unroll
        for (int kk = 0; kk < 16; kk++) {
            uint32_t p0 = f2tf(sa[kk][0]), p1 = f2tf(sa[kk][1]);
            uint32_t p2 = f2tf(sa[kk][2]), p3 = f2tf(sa[kk][3]);
            uint32_t u0 = __shfl_sync(0xffffffffu, p0, s0);
            uint32_t u1 = __shfl_sync(0xffffffffu, p1, s0);
            uint32_t v0 = __shfl_sync(0xffffffffu, p2, s0);
            uint32_t v1 = __shfl_sync(0xffffffffu, p3, s0);
            uint32_t w0 = __shfl_sync(0xffffffffu, p0, s1);
            uint32_t w1 = __shfl_sync(0xffffffffu, p1, s1);
            uint32_t x0 = __shfl_sync(0xffffffffu, p2, s1);
            uint32_t x1 = __shfl_sync(0xffffffffu, p3, s1);
            uint32_t af[4];
            af[0] = hi ? u1 : u0;  af[1] = hi ? v1 : v0;
            af[2] = hi ? w1 : w0;  af[3] = hi ? x1 : x0;
            const uint32_t* vrow0 = Vb + (kk * 8 + qc) * VROW + qr;
            #pragma unroll
            for (int nt = 0; nt < 8; nt++) {
                uint32_t bf[2] = { vrow0[nt * 8], vrow0[4 * VROW + nt * 8] };
                mma_tf32(oa[nt], af, bf);
            }
        }

        cp_wait0();
        __syncthreads();
    }

    // epilogue (rounded: feeds WO GEMM)
    float rA = 1.f / lA, rB = 1.f / lB;
    long rowA = tokbase + wid * 16 + qr;
    float* OA = Og + rowA * HIDDEN + h * HEAD_DIM;
    float* OB = OA + 8 * HIDDEN;
    #pragma unroll
    for (int nt = 0; nt < 8; nt++) {
        int col = nt * 8 + 2 * qc;
        *reinterpret_cast<float2*>(OA + col) = make_float2(tfr(oa[nt][0] * rA), tfr(oa[nt][1] * rA));
        *reinterpret_cast<float2*>(OB + col) = make_float2(tfr(oa[nt][2] * rB), tfr(oa[nt][3] * rB));
    }
}

// ---------------- cp.async TF32 GEMM, 128x128, 2 CTAs/SM ----------------
template<int EPI>
__global__ __launch_bounds__(256, 2)
void gemm_ca(const float* __restrict__ A, int lda,
             const float* __restrict__ B, int ldb,
             float* __restrict__ C, int ldc, int K,
             const float* __restrict__ bias,
             const float* __restrict__ resid, int ldr)
{
    constexpr int MT = 4, NT = 4;
    constexpr int BUF = 8192;
    extern __shared__ uint32_t sm[];
    uint32_t sbase = smem_u32(sm);

    int tid = threadIdx.x, lane = tid & 31, wid = tid >> 5;
    int wr = wid >> 2, wc = wid & 3;
    int m0 = blockIdx.y * 128, n0 = blockIdx.x * 128;

    const float* Ag = A + (long)m0 * lda;
    const float* Bg = B + (long)n0 * ldb;

    int srow = tid >> 3, sc = tid & 7;
    int rA = wr * 64 + ((lane >> 3) & 1) * 8 + (lane & 7);
    int rB = wc * 32 + (lane >> 4) * 8 + (lane & 7);
    int a7 = rA & 7, b7 = rB & 7;
    int hiA = lane >> 4, hiB = (lane >> 3) & 1;

    float acc[MT][NT][4];
    #pragma unroll
    for (int i = 0; i < MT; i++)
        #pragma unroll
        for (int j = 0; j < NT; j++)
            #pragma unroll
            for (int e = 0; e < 4; e++) acc[i][j][e] = 0.f;

    int nCh = K >> 5;

    #pragma unroll
    for (int i = 0; i < 4; i++) {
        int row = srow + i * 32;
        int u = sc ^ (row & 7);
        cp16(sbase + ((row * 32 + u * 4) << 2), Ag + (long)row * lda + sc * 4);
        cp16(sbase + ((4096 + row * 32 + u * 4) << 2), Bg + (long)row * ldb + sc * 4);
    }
    cp_commit();

    for (int c = 0; c < nCh; ++c) {
        int buf = c & 1;
        cp_wait0();
        __syncthreads();
        if (c + 1 < nCh) {
            const float* An = Ag + (c + 1) * 32;
            const float* Bn = Bg + (c + 1) * 32;
            uint32_t dst = sbase + (((buf ^ 1) * BUF) << 2);
            #pragma unroll
            for (int i = 0; i < 4; i++) {
                int row = srow + i * 32;
                int u = sc ^ (row & 7);
                cp16(dst + ((row * 32 + u * 4) << 2), An + (long)row * lda + sc * 4);
                cp16(dst + ((4096 + row * 32 + u * 4) << 2), Bn + (long)row * ldb + sc * 4);
            }
            cp_commit();
        }

        uint32_t aB = sbase + ((buf * BUF) << 2);
        uint32_t bB = aB + (4096 << 2);

        #pragma unroll
        for (int ks = 0; ks < 4; ++ks) {
            uint32_t af[MT][4], bf[NT][2];
            int uA = ((ks * 2 + hiA) ^ a7) * 4;
            int uB = ((ks * 2 + hiB) ^ b7) * 4;
            #pragma unroll
            for (int mt = 0; mt < MT; mt++)
                ldsm4(af[mt], aB + (((rA + mt * 16) * 32 + uA) << 2));
            #pragma unroll
            for (int ntp = 0; ntp < 2; ntp++)
                ldsm4(&bf[2 * ntp][0], bB + (((rB + ntp * 16) * 32 + uB) << 2));
            #pragma unroll
            for (int mt = 0; mt < MT; mt++)
                #pragma unroll
                for (int nt = 0; nt < NT; nt++)
                    mma_tf32(acc[mt][nt], af[mt], bf[nt]);
        }
        __syncthreads();
    }

    int qr = lane >> 2, qc = lane & 3;
    #pragma unroll
    for (int mt = 0; mt < MT; mt++) {
        #pragma unroll
        for (int half = 0; half < 2; half++) {
            int row = m0 + wr * 64 + mt * 16 + qr + half * 8;
            float* Crow = C + (long)row * ldc;
            const float* Rrow = (EPI == 1) ? (resid + (long)row * ldr) : nullptr;
            #pragma unroll
            for (int nt = 0; nt < NT; nt++) {
                int col = n0 + wc * 32 + nt * 8 + 2 * qc;
                float v0 = acc[mt][nt][half * 2 + 0];
                float v1 = acc[mt][nt][half * 2 + 1];
                if (EPI == 1) {
                    v0 += bias[col]     + Rrow[col];
                    v1 += bias[col + 1] + Rrow[col + 1];
                } else if (EPI == 2) {
                    v0 += bias[col];
                    v1 += bias[col + 1];
                    v0 = tfr(0.5f * v0 * (1.0f + erff(v0 * 0.70710678118654752f)));
                    v1 = tfr(0.5f * v1 * (1.0f + erff(v1 * 0.70710678118654752f)));
                } else {
                    v0 = tfr(v0); v1 = tfr(v1);
                }
                *reinterpret_cast<float2*>(&Crow[col]) = make_float2(v0, v1);
            }
        }
    }
}

// ---------------- launcher ----------------
extern "C" void kernel_launch(void* const* d_in, const int* in_sizes, int n_in,
                              void* d_out, int out_size)
{
    const float* x    = (const float*)d_in[0];
    const float* ln1g = (const float*)d_in[1];
    const float* ln1b = (const float*)d_in[2];
    const float* wq   = (const float*)d_in[3];
    const float* wk   = (const float*)d_in[4];
    const float* wv   = (const float*)d_in[5];
    const float* wo   = (const float*)d_in[6];
    const float* bo   = (const float*)d_in[7];
    const float* ln2g = (const float*)d_in[8];
    const float* ln2b = (const float*)d_in[9];
    const float* w1   = (const float*)d_in[10];
    const float* b1   = (const float*)d_in[11];
    const float* w2   = (const float*)d_in[12];
    const float* b2   = (const float*)d_in[13];
    float* out = (float*)d_out;

    float *xn, *qkv, *attn, *x1, *hm, *w1t, *w2t, *rwqkv, *rwo;
    cudaGetSymbolAddress((void**)&xn,    g_xn);
    cudaGetSymbolAddress((void**)&qkv,   g_qkv);
    cudaGetSymbolAddress((void**)&attn,  g_attn);
    cudaGetSymbolAddress((void**)&x1,    g_x1);
    cudaGetSymbolAddress((void**)&hm,    g_h);
    cudaGetSymbolAddress((void**)&w1t,   g_w1t);
    cudaGetSymbolAddress((void**)&w2t,   g_w2t);
    cudaGetSymbolAddress((void**)&rwqkv, g_wqkv);
    cudaGetSymbolAddress((void**)&rwo,   g_wo);

    float* qb = qkv;
    float* kb = qkv + (size_t)MTOK * HIDDEN;
    float* vb = qkv + (size_t)2 * MTOK * HIDDEN;
    float* rwq = rwqkv;
    float* rwk = rwqkv + (size_t)HIDDEN * HIDDEN;
    float* rwv = rwqkv + (size_t)2 * HIDDEN * HIDDEN;

    const int SMGE = 2 * 8192 * 4;                       // 65536
    const int SMFL = (3 * KWORDS + 2 * VWORDS) * 4;      // 167936
    cudaFuncSetAttribute((const void*)gemm_ca<0>, cudaFuncAttributeMaxDynamicSharedMemorySize, SMGE);
    cudaFuncSetAttribute((const void*)gemm_ca<1>, cudaFuncAttributeMaxDynamicSharedMemorySize, SMGE);
    cudaFuncSetAttribute((const void*)gemm_ca<2>, cudaFuncAttributeMaxDynamicSharedMemorySize, SMGE);
    cudaFuncSetAttribute((const void*)flash_k, cudaFuncAttributeMaxDynamicSharedMemorySize, SMFL);

    // prep
    int nw = HIDDEN * HIDDEN / 4;
    qkvpack_k<<<(3 * nw + 255) / 256, 256>>>(wq, wk, wv, rwqkv);
    roundcpy_k<<<(nw + 255) / 256, 256>>>(wo, rwo, nw);
    transpose_k<<<dim3(MLPH / 32, HIDDEN / 32), 256>>>(w1, MLPH, w1t, HIDDEN);
    transpose_k<<<dim3(HIDDEN / 32, MLPH / 32), 256>>>(w2, HIDDEN, w2t, MLPH);

    // 1. LN1
    ln_k<<<MTOK, 256>>>(x, ln1g, ln1b, xn);

    // 2. QKV: three GEMMs (R7 structure), dense outputs
    dim3 gQ(HIDDEN / 128, MTOK / 128);
    gemm_ca<0><<<gQ, 256, SMGE>>>(xn, HIDDEN, rwq, HIDDEN, qb, HIDDEN, HIDDEN, nullptr, nullptr, 0);
    gemm_ca<0><<<gQ, 256, SMGE>>>(xn, HIDDEN, rwk, HIDDEN, kb, HIDDEN, HIDDEN, nullptr, nullptr, 0);
    gemm_ca<0><<<gQ, 256, SMGE>>>(xn, HIDDEN, rwv, HIDDEN, vb, HIDDEN, HIDDEN, nullptr, nullptr, 0);

    // 3. fused attention (async-pipelined)
    flash_k<<<dim3(SEQ / 128, BATCH * HEADS), 256, SMFL>>>(qb, kb, vb, attn);

    // 4. x1 = attn @ wo^T + bo + x
    gemm_ca<1><<<gQ, 256, SMGE>>>(attn, HIDDEN, rwo, HIDDEN, x1, HIDDEN, HIDDEN, bo, x, HIDDEN);

    // 5. LN2
    ln_k<<<MTOK, 256>>>(x1, ln2g, ln2b, xn);

    // 6. h = gelu(xn @ w1 + b1)
    gemm_ca<2><<<dim3(MLPH / 128, MTOK / 128), 256, SMGE>>>(
        xn, HIDDEN, w1t, HIDDEN, hm, MLPH, HIDDEN, b1, nullptr, 0);

    // 7. out = h @ w2 + b2 + x1
    gemm_ca<1><<<gQ, 256, SMGE>>>(hm, MLPH, w2t, MLPH, out, HIDDEN, MLPH, b2, x1, HIDDEN);
}

// round 11
// speedup vs baseline: 1.9702x; 1.9082x over previous
#include <cuda_runtime.h>
#include <cuda_fp16.h>
#include <math.h>
#include <stdint.h>

// ---------------- problem constants ----------------
#define HIDDEN   768
#define MLPH     3072
#define HEADS    12
#define HEAD_DIM 64
#define BATCH    16
#define SEQ      1024
#define MTOK     (BATCH * SEQ)

// ---------------- scratch (device globals; no allocation) ----------------
__device__ __align__(16) __half g_xn  [(size_t)MTOK * HIDDEN];
__device__ __align__(16) __half g_qkv [(size_t)3 * MTOK * HIDDEN];
__device__ __align__(16) __half g_attn[(size_t)MTOK * HIDDEN];
__device__ __align__(16) float  g_x1  [(size_t)MTOK * HIDDEN];
__device__ __align__(16) __half g_h   [(size_t)MTOK * MLPH];
__device__ __align__(16) __half g_w1t [(size_t)MLPH * HIDDEN];
__device__ __align__(16) __half g_w2t [(size_t)HIDDEN * MLPH];
__device__ __align__(16) __half g_wqkv[(size_t)3 * HIDDEN * HIDDEN];
__device__ __align__(16) __half g_wo  [(size_t)HIDDEN * HIDDEN];

// ---------------- helpers ----------------
__device__ __forceinline__ uint32_t smem_u32(const void* p) {
    uint32_t a;
    asm("{ .reg .u64 t; cvta.to.shared.u64 t, %1; cvt.u32.u64 %0, t; }" : "=r"(a) : "l"(p));
    return a;
}
__device__ __forceinline__ void ldsm4(uint32_t* r, uint32_t addr) {
    asm volatile("ldmatrix.sync.aligned.m8n8.x4.shared.b16 {%0,%1,%2,%3}, [%4];"
                 : "=r"(r[0]), "=r"(r[1]), "=r"(r[2]), "=r"(r[3]) : "r"(addr));
}
__device__ __forceinline__ void ldsm4t(uint32_t* r, uint32_t addr) {
    asm volatile("ldmatrix.sync.aligned.m8n8.x4.trans.shared.b16 {%0,%1,%2,%3}, [%4];"
                 : "=r"(r[0]), "=r"(r[1]), "=r"(r[2]), "=r"(r[3]) : "r"(addr));
}
__device__ __forceinline__ void cp16(uint32_t saddr, const void* g) {
    asm volatile("cp.async.ca.shared.global [%0], [%1], 16;" :: "r"(saddr), "l"(g) : "memory");
}
__device__ __forceinline__ void cp_commit() {
    asm volatile("cp.async.commit_group;" ::: "memory");
}
__device__ __forceinline__ void cp_wait0() {
    asm volatile("cp.async.wait_group 0;" ::: "memory");
}
// fp16 tensor-core mma: D(fp32) += A(fp16) * B(fp16)
__device__ __forceinline__ void mma_h(float* d, const uint32_t* a, const uint32_t* b) {
    asm volatile("mma.sync.aligned.m16n8k16.row.col.f32.f16.f16.f32 "
                 "{%0,%1,%2,%3}, {%4,%5,%6,%7}, {%8,%9}, {%0,%1,%2,%3};"
                 : "+f"(d[0]), "+f"(d[1]), "+f"(d[2]), "+f"(d[3])
                 : "r"(a[0]), "r"(a[1]), "r"(a[2]), "r"(a[3]), "r"(b[0]), "r"(b[1]));
}
// pack two fp32 -> fp16x2 (lo first)
#define PACKH2(r, lo, hi) \
    asm("cvt.rn.f16x2.f32 %0, %1, %2;" : "=r"(r) : "f"(hi), "f"(lo))

__device__ __forceinline__ float warp_sum(float v) {
    #pragma unroll
    for (int o = 16; o; o >>= 1) v += __shfl_xor_sync(0xffffffffu, v, o);
    return v;
}

// ---------------- prep: pack QKV weights (fp16) ----------------
__global__ __launch_bounds__(256)
void qkvpack_k(const float* __restrict__ wq, const float* __restrict__ wk,
               const float* __restrict__ wv, __half* __restrict__ dst)
{
    const int N4 = HIDDEN * HIDDEN / 4;
    int i = blockIdx.x * 256 + threadIdx.x;
    if (i >= 3 * N4) return;
    const float* src = (i < N4) ? wq : (i < 2 * N4) ? wk : wv;
    int j = (i < N4) ? i : (i < 2 * N4) ? i - N4 : i - 2 * N4;
    float4 v = reinterpret_cast<const float4*>(src)[j];
    __half2* d = reinterpret_cast<__half2*>(dst);
    d[2 * i + 0] = __floats2half2_rn(v.x, v.y);
    d[2 * i + 1] = __floats2half2_rn(v.z, v.w);
}

__global__ __launch_bounds__(256)
void halfcpy_k(const float* __restrict__ in, __half* __restrict__ out, int n4)
{
    int i = blockIdx.x * 256 + threadIdx.x;
    if (i < n4) {
        float4 v = reinterpret_cast<const float4*>(in)[i];
        __half2* d = reinterpret_cast<__half2*>(out);
        d[2 * i + 0] = __floats2half2_rn(v.x, v.y);
        d[2 * i + 1] = __floats2half2_rn(v.z, v.w);
    }
}

// ---------------- LayerNorm (fp32 in, fp16 out) ----------------
__global__ __launch_bounds__(256)
void ln_k(const float* __restrict__ x, const float* __restrict__ g,
          const float* __restrict__ b, __half* __restrict__ out)
{
    long row = blockIdx.x;
    const float* xr = x + row * (long)HIDDEN;
    int tid = threadIdx.x;
    float v0 = xr[tid], v1 = xr[tid + 256], v2 = xr[tid + 512];
    float s  = v0 + v1 + v2;
    float s2 = v0 * v0 + v1 * v1 + v2 * v2;
    __shared__ float sh[18];
    s = warp_sum(s); s2 = warp_sum(s2);
    int w = tid >> 5, l = tid & 31;
    if (!l) { sh[w] = s; sh[w + 8] = s2; }
    __syncthreads();
    if (tid == 0) {
        float ts = 0.f, ts2 = 0.f;
        #pragma unroll
        for (int i = 0; i < 8; i++) { ts += sh[i]; ts2 += sh[i + 8]; }
        float mu  = ts * (1.0f / HIDDEN);
        float var = ts2 * (1.0f / HIDDEN) - mu * mu;
        sh[16] = mu; sh[17] = rsqrtf(var + 1e-5f);
    }
    __syncthreads();
    float mu = sh[16], inv = sh[17];
    __half* o = out + row * (long)HIDDEN;
    o[tid]       = __float2half_rn((v0 - mu) * inv * g[tid]       + b[tid]);
    o[tid + 256] = __float2half_rn((v1 - mu) * inv * g[tid + 256] + b[tid + 256]);
    o[tid + 512] = __float2half_rn((v2 - mu) * inv * g[tid + 512] + b[tid + 512]);
}

// ---------------- transpose fp32 -> fp16 (weights) ----------------
__global__ __launch_bounds__(256)
void transpose_k(const float* __restrict__ in, int ldi,
                 __half* __restrict__ out, int ldo)
{
    __shared__ float t[32][33];
    int c0 = blockIdx.x * 32, r0 = blockIdx.y * 32;
    int tx = threadIdx.x & 31, ty = threadIdx.x >> 5;
    #pragma unroll
    for (int i = ty; i < 32; i += 8)
        t[i][tx] = in[(long)(r0 + i) * ldi + c0 + tx];
    __syncthreads();
    #pragma unroll
    for (int i = ty; i < 32; i += 8)
        out[(long)(c0 + i) * ldo + r0 + tx] = __float2half_rn(t[tx][i]);
}

// ---------------- flash attention (fp16 operands, fp32 accum) ----------------
// Q/K/V tiles: 128 rows x 64 halfs, padded to 144B pitch (bank-conflict-free
// ldmatrix: (36r)%32 bank quads are a bijection over 8 consecutive rows).
#define FPITCH 144                  // bytes per row
#define TILEB  (128 * FPITCH)       // 18432 bytes per tile

__global__ __launch_bounds__(256)
void flash_k(const __half* __restrict__ Qb, const __half* __restrict__ Kb,
             const __half* __restrict__ Vg, __half* __restrict__ Og)
{
    extern __shared__ char sm[];
    uint32_t qsb = smem_u32(sm);
    uint32_t ksb = qsb + TILEB;          // 2 buffers
    uint32_t vsb = qsb + 3 * TILEB;      // 2 buffers

    int tid = threadIdx.x, lane = tid & 31, wid = tid >> 5;
    int qr = lane >> 2, qc = lane & 3;
    int z = blockIdx.y;
    int b = z / HEADS, h = z - b * HEADS;
    int q0 = blockIdx.x * 128;
    long tokbase = (long)b * SEQ + q0;

    const __half* Qp = Qb + tokbase * HIDDEN + h * HEAD_DIM;
    const __half* Kp = Kb + (long)b * SEQ * HIDDEN + h * HEAD_DIM;
    const __half* Vp = Vg + (long)b * SEQ * HIDDEN + h * HEAD_DIM;

    // prologue: async Q + K0 + V0 (128 rows x 8 units of 16B each)
    #pragma unroll
    for (int i = 0; i < 4; i++) {
        int f = tid + i * 256; int r = f >> 1, u = (f & 1) * 4;
        // 2 units per (thread,iter) pair via two cp16s keeps code simple:
        #pragma unroll
        for (int uu = 0; uu < 4; uu++) {
            // covered below
        }
    }
    // simpler: 1024 units per tile, 4 per thread
    #pragma unroll
    for (int i = 0; i < 4; i++) {
        int f = tid + i * 256; int r = f >> 3, u = f & 7;
        cp16(qsb + r * FPITCH + u * 16, Qp + (long)r * HIDDEN + u * 8);
        cp16(ksb + r * FPITCH + u * 16, Kp + (long)r * HIDDEN + u * 8);
        cp16(vsb + r * FPITCH + u * 16, Vp + (long)r * HIDDEN + u * 8);
    }
    cp_commit();
    cp_wait0();
    __syncthreads();

    // Q fragments: 4 ksteps of k16 over 64 dims
    int rQ = wid * 16 + ((lane >> 3) & 1) * 8 + (lane & 7);
    int hiQ = lane >> 4;
    uint32_t qf[4][4];
    #pragma unroll
    for (int ks = 0; ks < 4; ks++)
        ldsm4(qf[ks], qsb + rQ * FPITCH + ks * 32 + hiQ * 16);

    // K B-frag lane base
    int rK = ((lane >> 4) & 1) * 8 + (lane & 7);
    int hiK = (lane >> 3) & 1;
    // V trans-frag lane base
    int rV = ((lane >> 3) & 1) * 8 + (lane & 7);
    int hiV = lane >> 4;

    float oa[8][4];
    #pragma unroll
    for (int i = 0; i < 8; i++)
        #pragma unroll
        for (int e = 0; e < 4; e++) oa[i][e] = 0.f;
    float mA = -1e30f, mB = -1e30f, lA = 0.f, lB = 0.f;
    const float scale = 0.125f;

    for (int ch = 0; ch < SEQ / 128; ch++) {
        int buf = ch & 1;
        uint32_t kbuf = ksb + buf * TILEB;
        uint32_t vbuf = vsb + buf * TILEB;

        // S = Q @ K^T  (16 x 128 per warp, 4 k16 steps)
        float sa[16][4];
        #pragma unroll
        for (int i = 0; i < 16; i++)
            #pragma unroll
            for (int e = 0; e < 4; e++) sa[i][e] = 0.f;
        #pragma unroll
        for (int ks = 0; ks < 4; ks++) {
            #pragma unroll
            for (int ntp = 0; ntp < 8; ntp++) {
                uint32_t bf[4];
                ldsm4(bf, kbuf + (rK + ntp * 16) * FPITCH + ks * 32 + hiK * 16);
                mma_h(sa[2 * ntp + 0], qf[ks], bf);
                mma_h(sa[2 * ntp + 1], qf[ks], bf + 2);
            }
        }

        // async prefetch K(c+1), V(c+1)
        if (ch + 1 < SEQ / 128) {
            const __half* Kn = Kp + (long)(ch + 1) * 128 * HIDDEN;
            const __half* Vn = Vp + (long)(ch + 1) * 128 * HIDDEN;
            uint32_t kdst = ksb + (buf ^ 1) * TILEB;
            uint32_t vdst = vsb + (buf ^ 1) * TILEB;
            #pragma unroll
            for (int i = 0; i < 4; i++) {
                int f = tid + i * 256; int r = f >> 3, u = f & 7;
                cp16(kdst + r * FPITCH + u * 16, Kn + (long)r * HIDDEN + u * 8);
                cp16(vdst + r * FPITCH + u * 16, Vn + (long)r * HIDDEN + u * 8);
            }
            cp_commit();
        }

        // online softmax
        float rmA = -1e30f, rmB = -1e30f;
        #pragma unroll
        for (int nt = 0; nt < 16; nt++) {
            rmA = fmaxf(rmA, fmaxf(sa[nt][0], sa[nt][1]));
            rmB = fmaxf(rmB, fmaxf(sa[nt][2], sa[nt][3]));
        }
        rmA = fmaxf(rmA, __shfl_xor_sync(0xffffffffu, rmA, 1));
        rmA = fmaxf(rmA, __shfl_xor_sync(0xffffffffu, rmA, 2));
        rmB = fmaxf(rmB, __shfl_xor_sync(0xffffffffu, rmB, 1));
        rmB = fmaxf(rmB, __shfl_xor_sync(0xffffffffu, rmB, 2));
        float mAn = fmaxf(mA, rmA), mBn = fmaxf(mB, rmB);
        float aA = __expf((mA - mAn) * scale), aB = __expf((mB - mBn) * scale);
        float sA = 0.f, sB = 0.f;
        #pragma unroll
        for (int nt = 0; nt < 16; nt++) {
            sa[nt][0] = __expf((sa[nt][0] - mAn) * scale);
            sa[nt][1] = __expf((sa[nt][1] - mAn) * scale);
            sa[nt][2] = __expf((sa[nt][2] - mBn) * scale);
            sa[nt][3] = __expf((sa[nt][3] - mBn) * scale);
            sA += sa[nt][0] + sa[nt][1];
            sB += sa[nt][2] + sa[nt][3];
        }
        sA += __shfl_xor_sync(0xffffffffu, sA, 1);
        sA += __shfl_xor_sync(0xffffffffu, sA, 2);
        sB += __shfl_xor_sync(0xffffffffu, sB, 1);
        sB += __shfl_xor_sync(0xffffffffu, sB, 2);
        lA = aA * lA + sA;  lB = aB * lB + sB;
        mA = mAn;  mB = mBn;
        #pragma unroll
        for (int nt = 0; nt < 8; nt++) {
            oa[nt][0] *= aA; oa[nt][1] *= aA;
            oa[nt][2] *= aB; oa[nt][3] *= aB;
        }

        // O += P @ V : P accum pairs ARE fp16 A-frag pairs (no shuffles).
        // V[key][dim] via ldmatrix.trans gives B-frags directly.
        #pragma unroll
        for (int j = 0; j < 8; j++) {
            uint32_t af[4];
            PACKH2(af[0], sa[2 * j][0],     sa[2 * j][1]);
            PACKH2(af[1], sa[2 * j][2],     sa[2 * j][3]);
            PACKH2(af[2], sa[2 * j + 1][0], sa[2 * j + 1][1]);
            PACKH2(af[3], sa[2 * j + 1][2], sa[2 * j + 1][3]);
            #pragma unroll
            for (int dp = 0; dp < 4; dp++) {
                uint32_t bf[4];
                ldsm4t(bf, vbuf + (16 * j + rV) * FPITCH + dp * 32 + hiV * 16);
                mma_h(oa[2 * dp + 0], af, bf);
                mma_h(oa[2 * dp + 1], af, bf + 2);
            }
        }

        cp_wait0();
        __syncthreads();
    }

    // epilogue: normalize, store fp16 attn
    float rA = 1.f / lA, rB = 1.f / lB;
    long rowA = tokbase + wid * 16 + qr;
    __half* OA = Og + rowA * HIDDEN + h * HEAD_DIM;
    __half* OB = OA + 8 * HIDDEN;
    #pragma unroll
    for (int nt = 0; nt < 8; nt++) {
        int col = nt * 8 + 2 * qc;
        *reinterpret_cast<__half2*>(OA + col) = __floats2half2_rn(oa[nt][0] * rA, oa[nt][1] * rA);
        *reinterpret_cast<__half2*>(OB + col) = __floats2half2_rn(oa[nt][2] * rB, oa[nt][3] * rB);
    }
}

// ---------------- fp16 cp.async GEMM, 128x128, BK=64, 2 CTAs/SM ----------------
// C = A[M,K] @ B[N,K]^T, fp32 accum.
// EPI: 0 -> fp16 store; 1 -> fp32 +bias+resid; 2 -> fp16 +bias+GELU.
template<int EPI>
__global__ __launch_bounds__(256, 2)
void gemm_h(const __half* __restrict__ A, int lda,
            const __half* __restrict__ B, int ldb,
            void* __restrict__ Cv, int ldc, int K,
            const float* __restrict__ bias,
            const float* __restrict__ resid, int ldr)
{
    constexpr int MT = 4, NT = 4;
    constexpr int ABUF = 2 * TILEB;          // stride between buffers (A+B)
    extern __shared__ char sm[];
    uint32_t sbase = smem_u32(sm);

    int tid = threadIdx.x, lane = tid & 31, wid = tid >> 5;
    int wr = wid >> 2, wc = wid & 3;
    int m0 = blockIdx.y * 128, n0 = blockIdx.x * 128;

    const __half* Ag = A + (long)m0 * lda;
    const __half* Bg = B + (long)n0 * ldb;

    int rA = wr * 64 + ((lane >> 3) & 1) * 8 + (lane & 7);
    int hiA = lane >> 4;
    int rB = wc * 32 + ((lane >> 4) & 1) * 8 + (lane & 7);
    int hiB = (lane >> 3) & 1;

    float acc[MT][NT][4];
    #pragma unroll
    for (int i = 0; i < MT; i++)
        #pragma unroll
        for (int j = 0; j < NT; j++)
            #pragma unroll
            for (int e = 0; e < 4; e++) acc[i][j][e] = 0.f;

    int nCh = K >> 6;   // 64 halfs per chunk

    // prologue: chunk 0 -> buffer 0 (1024 units per tile, 4/thread)
    #pragma unroll
    for (int i = 0; i < 4; i++) {
        int f = tid + i * 256; int r = f >> 3, u = f & 7;
        cp16(sbase + r * FPITCH + u * 16, Ag + (long)r * lda + u * 8);
        cp16(sbase + TILEB + r * FPITCH + u * 16, Bg + (long)r * ldb + u * 8);
    }
    cp_commit();

    for (int c = 0; c < nCh; ++c) {
        int buf = c & 1;
        cp_wait0();
        __syncthreads();
        if (c + 1 < nCh) {
            const __half* An = Ag + (c + 1) * 64;
            const __half* Bn = Bg + (c + 1) * 64;
            uint32_t dst = sbase + (buf ^ 1) * ABUF;
            #pragma unroll
            for (int i = 0; i < 4; i++) {
                int f = tid + i * 256; int r = f >> 3, u = f & 7;
                cp16(dst + r * FPITCH + u * 16, An + (long)r * lda + u * 8);
                cp16(dst + TILEB + r * FPITCH + u * 16, Bn + (long)r * ldb + u * 8);
            }
            cp_commit();
        }

        uint32_t aB = sbase + buf * ABUF;
        uint32_t bB = aB + TILEB;

        #pragma unroll
        for (int ks = 0; ks < 4; ++ks) {
            uint32_t af[MT][4], bf[NT / 2][4];
            #pragma unroll
            for (int mt = 0; mt < MT; mt++)
                ldsm4(af[mt], aB + (rA + mt * 16) * FPITCH + ks * 32 + hiA * 16);
            #pragma unroll
            for (int ntp = 0; ntp < NT / 2; ntp++)
                ldsm4(bf[ntp], bB + (rB + ntp * 16) * FPITCH + ks * 32 + hiB * 16);
            #pragma unroll
            for (int mt = 0; mt < MT; mt++)
                #pragma unroll
                for (int ntp = 0; ntp < NT / 2; ntp++) {
                    mma_h(acc[mt][2 * ntp + 0], af[mt], bf[ntp]);
                    mma_h(acc[mt][2 * ntp + 1], af[mt], bf[ntp] + 2);
                }
        }
        __syncthreads();
    }

    int qr = lane >> 2, qc = lane & 3;
    #pragma unroll
    for (int mt = 0; mt < MT; mt++) {
        #pragma unroll
        for (int half = 0; half < 2; half++) {
            int row = m0 + wr * 64 + mt * 16 + qr + half * 8;
            const float* Rrow = (EPI == 1) ? (resid + (long)row * ldr) : nullptr;
            #pragma unroll
            for (int nt = 0; nt < NT; nt++) {
                int col = n0 + wc * 32 + nt * 8 + 2 * qc;
                float v0 = acc[mt][nt][half * 2 + 0];
                float v1 = acc[mt][nt][half * 2 + 1];
                if (EPI == 1) {
                    v0 += bias[col]     + Rrow[col];
                    v1 += bias[col + 1] + Rrow[col + 1];
                    float* Crow = (float*)Cv + (long)row * ldc;
                    *reinterpret_cast<float2*>(&Crow[col]) = make_float2(v0, v1);
                } else {
                    if (EPI == 2) {
                        v0 += bias[col];
                        v1 += bias[col + 1];
                        v0 = 0.5f * v0 * (1.0f + erff(v0 * 0.70710678118654752f));
                        v1 = 0.5f * v1 * (1.0f + erff(v1 * 0.70710678118654752f));
                    }
                    __half* Crow = (__half*)Cv + (long)row * ldc;
                    *reinterpret_cast<__half2*>(&Crow[col]) = __floats2half2_rn(v0, v1);
                }
            }
        }
    }
}

// ---------------- launcher ----------------
extern "C" void kernel_launch(void* const* d_in, const int* in_sizes, int n_in,
                              void* d_out, int out_size)
{
    const float* x    = (const float*)d_in[0];
    const float* ln1g = (const float*)d_in[1];
    const float* ln1b = (const float*)d_in[2];
    const float* wq   = (const float*)d_in[3];
    const float* wk   = (const float*)d_in[4];
    const float* wv   = (const float*)d_in[5];
    const float* wo   = (const float*)d_in[6];
    const float* bo   = (const float*)d_in[7];
    const float* ln2g = (const float*)d_in[8];
    const float* ln2b = (const float*)d_in[9];
    const float* w1   = (const float*)d_in[10];
    const float* b1   = (const float*)d_in[11];
    const float* w2   = (const float*)d_in[12];
    const float* b2   = (const float*)d_in[13];
    float* out = (float*)d_out;

    __half *xn, *qkv, *attn, *hm, *w1t, *w2t, *rwqkv, *rwo;
    float* x1;
    cudaGetSymbolAddress((void**)&xn,    g_xn);
    cudaGetSymbolAddress((void**)&qkv,   g_qkv);
    cudaGetSymbolAddress((void**)&attn,  g_attn);
    cudaGetSymbolAddress((void**)&x1,    g_x1);
    cudaGetSymbolAddress((void**)&hm,    g_h);
    cudaGetSymbolAddress((void**)&w1t,   g_w1t);
    cudaGetSymbolAddress((void**)&w2t,   g_w2t);
    cudaGetSymbolAddress((void**)&rwqkv, g_wqkv);
    cudaGetSymbolAddress((void**)&rwo,   g_wo);

    __half* qb = qkv;
    __half* kb = qkv + (size_t)MTOK * HIDDEN;
    __half* vb = qkv + (size_t)2 * MTOK * HIDDEN;
    __half* rwq = rwqkv;
    __half* rwk = rwqkv + (size_t)HIDDEN * HIDDEN;
    __half* rwv = rwqkv + (size_t)2 * HIDDEN * HIDDEN;

    const int SMGE = 4 * TILEB;   // 73728: A,B double-buffered
    const int SMFL = 5 * TILEB;   // 92160: Q + 2K + 2V
    cudaFuncSetAttribute((const void*)gemm_h<0>, cudaFuncAttributeMaxDynamicSharedMemorySize, SMGE);
    cudaFuncSetAttribute((const void*)gemm_h<1>, cudaFuncAttributeMaxDynamicSharedMemorySize, SMGE);
    cudaFuncSetAttribute((const void*)gemm_h<2>, cudaFuncAttributeMaxDynamicSharedMemorySize, SMGE);
    cudaFuncSetAttribute((const void*)flash_k, cudaFuncAttributeMaxDynamicSharedMemorySize, SMFL);

    // prep
    int nw = HIDDEN * HIDDEN / 4;
    qkvpack_k<<<(3 * nw + 255) / 256, 256>>>(wq, wk, wv, rwqkv);
    halfcpy_k<<<(nw + 255) / 256, 256>>>(wo, rwo, nw);
    transpose_k<<<dim3(MLPH / 32, HIDDEN / 32), 256>>>(w1, MLPH, w1t, HIDDEN);
    transpose_k<<<dim3(HIDDEN / 32, MLPH / 32), 256>>>(w2, HIDDEN, w2t, MLPH);

    // 1. LN1 (fp16 out)
    ln_k<<<MTOK, 256>>>(x, ln1g, ln1b, xn);

    // 2. QKV: three fp16 GEMMs
    dim3 gQ(HIDDEN / 128, MTOK / 128);
    gemm_h<0><<<gQ, 256, SMGE>>>(xn, HIDDEN, rwq, HIDDEN, qb, HIDDEN, HIDDEN, nullptr, nullptr, 0);
    gemm_h<0><<<gQ, 256, SMGE>>>(xn, HIDDEN, rwk, HIDDEN, kb, HIDDEN, HIDDEN, nullptr, nullptr, 0);
    gemm_h<0><<<gQ, 256, SMGE>>>(xn, HIDDEN, rwv, HIDDEN, vb, HIDDEN, HIDDEN, nullptr, nullptr, 0);

    // 3. fused attention (fp16)
    flash_k<<<dim3(SEQ / 128, BATCH * HEADS), 256, SMFL>>>(qb, kb, vb, attn);

    // 4. x1 = attn @ wo^T + bo + x  (fp32 out)
    gemm_h<1><<<gQ, 256, SMGE>>>(attn, HIDDEN, rwo, HIDDEN, x1, HIDDEN, HIDDEN, bo, x, HIDDEN);

    // 5. LN2 (fp16 out)
    ln_k<<<MTOK, 256>>>(x1, ln2g, ln2b, xn);

    // 6. h = gelu(xn @ w1 + b1) (fp16 out)
    gemm_h<2><<<dim3(MLPH / 128, MTOK / 128), 256, SMGE>>>(
        xn, HIDDEN, w1t, HIDDEN, hm, MLPH, HIDDEN, b1, nullptr, 0);

    // 7. out = h @ w2 + b2 + x1 (fp32 out)
    gemm_h<1><<<gQ, 256, SMGE>>>(hm, MLPH, w2t, MLPH, out, HIDDEN, MLPH, b2, x1, HIDDEN);
}